// round 1
// baseline (speedup 1.0000x reference)
#include <cuda_runtime.h>

// Problem constants
#define BB 8
#define HH 512
#define EE 256
#define TT 2048
#define SS 2048
#define SCALE 0.8366600265340756f  // sqrt(0.7)

// Scratch (device globals — no allocation allowed in kernel_launch)
__device__ float g_Q[BB * TT * EE];    // 16.8 MB
__device__ float g_ctx[BB * TT * EE];  // 16.8 MB

// ======================================================================
// Shared 128x128x8 fp32 GEMM microkernel pattern: 256 threads, 8x8/thread
// ======================================================================

// ---- K1: Q[b,t,e] = SCALE * (sum_h dec[b,h,t]*W_h2e[e,h] + b_h2e[e] + embedd[b,t,e])
__global__ void __launch_bounds__(256) k1_q(
    const float* __restrict__ dec,   // [B,H,T]
    const float* __restrict__ emb,   // [B,T,E]
    const float* __restrict__ W,     // [E,H]
    const float* __restrict__ bias)  // [E]
{
    __shared__ float As[8][128];  // [k=h][m=t]
    __shared__ float Bs[8][128];  // [k=h][n=e]
    const int b  = blockIdx.z;
    const int tB = blockIdx.y * 128;
    const int eB = blockIdx.x * 128;
    const int tid = threadIdx.x;
    const int m0 = (tid >> 4) << 3;
    const int n0 = (tid & 15) << 3;
    const int a_h = tid >> 5;            // 0..7
    const int a_t = (tid & 31) << 2;     // 0..124
    const int b_e = tid >> 1;            // 0..127
    const int b_h = (tid & 1) << 2;      // 0 or 4
    const float* Ag = dec + (size_t)b * HH * TT;
    float acc[8][8] = {};
    for (int k0 = 0; k0 < HH; k0 += 8) {
        float4 av = *(const float4*)(Ag + (size_t)(k0 + a_h) * TT + tB + a_t);
        *(float4*)&As[a_h][a_t] = av;
        float4 bv = *(const float4*)(W + (size_t)(eB + b_e) * HH + k0 + b_h);
        Bs[b_h + 0][b_e] = bv.x; Bs[b_h + 1][b_e] = bv.y;
        Bs[b_h + 2][b_e] = bv.z; Bs[b_h + 3][b_e] = bv.w;
        __syncthreads();
#pragma unroll
        for (int k = 0; k < 8; k++) {
            float a[8], bb[8];
            *(float4*)&a[0]  = *(const float4*)&As[k][m0];
            *(float4*)&a[4]  = *(const float4*)&As[k][m0 + 4];
            *(float4*)&bb[0] = *(const float4*)&Bs[k][n0];
            *(float4*)&bb[4] = *(const float4*)&Bs[k][n0 + 4];
#pragma unroll
            for (int i = 0; i < 8; i++)
#pragma unroll
                for (int j = 0; j < 8; j++) acc[i][j] = fmaf(a[i], bb[j], acc[i][j]);
        }
        __syncthreads();
    }
#pragma unroll
    for (int i = 0; i < 8; i++) {
        const int t = tB + m0 + i;
        const size_t rowo = ((size_t)b * TT + t) * EE;
#pragma unroll
        for (int j = 0; j < 8; j += 4) {
            const int e = eB + n0 + j;
            float4 ev = *(const float4*)(emb + rowo + e);
            float4 bi = *(const float4*)(bias + e);
            float4 o;
            o.x = SCALE * (acc[i][j + 0] + bi.x + ev.x);
            o.y = SCALE * (acc[i][j + 1] + bi.y + ev.y);
            o.z = SCALE * (acc[i][j + 2] + bi.z + ev.z);
            o.w = SCALE * (acc[i][j + 3] + bi.w + ev.w);
            *(float4*)(g_Q + rowo + e) = o;
        }
    }
}

// ---- K2: energy[b,t,s] = sum_e Q[b,t,e] * K[b,s,e]   (written raw into a_out)
__global__ void __launch_bounds__(256) k2_energy(
    const float* __restrict__ Kmat,  // en_conved [B,S,E]
    float* __restrict__ a_out)       // [B,T,S]
{
    __shared__ float As[8][128];  // [k=e][m=t]
    __shared__ float Bs[8][128];  // [k=e][n=s]
    const int b  = blockIdx.z;
    const int tB = blockIdx.y * 128;
    const int sB = blockIdx.x * 128;
    const int tid = threadIdx.x;
    const int m0 = (tid >> 4) << 3;
    const int n0 = (tid & 15) << 3;
    const int lr = tid >> 1;          // 0..127
    const int lk = (tid & 1) << 2;    // 0 or 4
    const float* Qg = g_Q + (size_t)b * TT * EE;
    const float* Kg = Kmat + (size_t)b * SS * EE;
    float acc[8][8] = {};
    for (int k0 = 0; k0 < EE; k0 += 8) {
        float4 av = *(const float4*)(Qg + (size_t)(tB + lr) * EE + k0 + lk);
        As[lk + 0][lr] = av.x; As[lk + 1][lr] = av.y;
        As[lk + 2][lr] = av.z; As[lk + 3][lr] = av.w;
        float4 bv = *(const float4*)(Kg + (size_t)(sB + lr) * EE + k0 + lk);
        Bs[lk + 0][lr] = bv.x; Bs[lk + 1][lr] = bv.y;
        Bs[lk + 2][lr] = bv.z; Bs[lk + 3][lr] = bv.w;
        __syncthreads();
#pragma unroll
        for (int k = 0; k < 8; k++) {
            float a[8], bb[8];
            *(float4*)&a[0]  = *(const float4*)&As[k][m0];
            *(float4*)&a[4]  = *(const float4*)&As[k][m0 + 4];
            *(float4*)&bb[0] = *(const float4*)&Bs[k][n0];
            *(float4*)&bb[4] = *(const float4*)&Bs[k][n0 + 4];
#pragma unroll
            for (int i = 0; i < 8; i++)
#pragma unroll
                for (int j = 0; j < 8; j++) acc[i][j] = fmaf(a[i], bb[j], acc[i][j]);
        }
        __syncthreads();
    }
#pragma unroll
    for (int i = 0; i < 8; i++) {
        float* row = a_out + ((size_t)b * TT + tB + m0 + i) * SS + sB + n0;
#pragma unroll
        for (int j = 0; j < 8; j += 4) {
            float4 o = {acc[i][j], acc[i][j + 1], acc[i][j + 2], acc[i][j + 3]};
            *(float4*)(row + j) = o;
        }
    }
}

// ---- K3: in-place row softmax over S
__global__ void __launch_bounds__(256) k3_softmax(float* __restrict__ a)
{
    const size_t row = blockIdx.x;
    float* p = a + row * SS;
    const int tid = threadIdx.x;
    float v[8];
#pragma unroll
    for (int i = 0; i < 8; i++) v[i] = p[tid + (i << 8)];
    float m = v[0];
#pragma unroll
    for (int i = 1; i < 8; i++) m = fmaxf(m, v[i]);
#pragma unroll
    for (int o = 16; o > 0; o >>= 1) m = fmaxf(m, __shfl_xor_sync(0xffffffffu, m, o));
    __shared__ float red[8];
    if ((tid & 31) == 0) red[tid >> 5] = m;
    __syncthreads();
    float M = red[0];
#pragma unroll
    for (int i = 1; i < 8; i++) M = fmaxf(M, red[i]);
    float s = 0.f;
#pragma unroll
    for (int i = 0; i < 8; i++) { v[i] = expf(v[i] - M); s += v[i]; }
#pragma unroll
    for (int o = 16; o > 0; o >>= 1) s += __shfl_xor_sync(0xffffffffu, s, o);
    __syncthreads();  // protect red[] reuse
    if ((tid & 31) == 0) red[tid >> 5] = s;
    __syncthreads();
    float Z = 0.f;
#pragma unroll
    for (int i = 0; i < 8; i++) Z += red[i];
    const float inv = 1.f / Z;
#pragma unroll
    for (int i = 0; i < 8; i++) p[tid + (i << 8)] = v[i] * inv;
}

// ---- K4: ctx[b,t,e] = sum_s a[b,t,s] * V[b,s,e]
__global__ void __launch_bounds__(256) k4_context(
    const float* __restrict__ a,  // [B,T,S] normalized
    const float* __restrict__ V)  // en_combined [B,S,E]
{
    __shared__ float As[8][128];  // [k=s][m=t]
    __shared__ float Bs[8][128];  // [k=s][n=e]
    const int b  = blockIdx.z;
    const int tB = blockIdx.y * 128;
    const int eB = blockIdx.x * 128;
    const int tid = threadIdx.x;
    const int m0 = (tid >> 4) << 3;
    const int n0 = (tid & 15) << 3;
    const int la_r = tid >> 1;          // 0..127
    const int la_k = (tid & 1) << 2;    // 0 or 4
    const int lb_s = tid >> 5;          // 0..7
    const int lb_e = (tid & 31) << 2;   // 0..124
    const float* Ag = a + (size_t)b * TT * SS;
    const float* Vg = V + (size_t)b * SS * EE;
    float acc[8][8] = {};
    for (int k0 = 0; k0 < SS; k0 += 8) {
        float4 av = *(const float4*)(Ag + (size_t)(tB + la_r) * SS + k0 + la_k);
        As[la_k + 0][la_r] = av.x; As[la_k + 1][la_r] = av.y;
        As[la_k + 2][la_r] = av.z; As[la_k + 3][la_r] = av.w;
        float4 bv = *(const float4*)(Vg + (size_t)(k0 + lb_s) * EE + eB + lb_e);
        *(float4*)&Bs[lb_s][lb_e] = bv;
        __syncthreads();
#pragma unroll
        for (int k = 0; k < 8; k++) {
            float av2[8], bb[8];
            *(float4*)&av2[0] = *(const float4*)&As[k][m0];
            *(float4*)&av2[4] = *(const float4*)&As[k][m0 + 4];
            *(float4*)&bb[0]  = *(const float4*)&Bs[k][n0];
            *(float4*)&bb[4]  = *(const float4*)&Bs[k][n0 + 4];
#pragma unroll
            for (int i = 0; i < 8; i++)
#pragma unroll
                for (int j = 0; j < 8; j++) acc[i][j] = fmaf(av2[i], bb[j], acc[i][j]);
        }
        __syncthreads();
    }
#pragma unroll
    for (int i = 0; i < 8; i++) {
        const size_t rowo = ((size_t)b * TT + tB + m0 + i) * EE;
#pragma unroll
        for (int j = 0; j < 8; j += 4) {
            float4 o = {acc[i][j], acc[i][j + 1], acc[i][j + 2], acc[i][j + 3]};
            *(float4*)(g_ctx + rowo + eB + n0 + j) = o;
        }
    }
}

// ---- K5: out[b,h,t] = SCALE*(sum_e ctx[b,t,e]*W_e2h[h,e] + b_e2h[h] + dec[b,h,t])
__global__ void __launch_bounds__(256) k5_out(
    const float* __restrict__ dec,   // [B,H,T]
    const float* __restrict__ W,     // [H,E]
    const float* __restrict__ bias,  // [H]
    float* __restrict__ out)         // [B,H,T]
{
    __shared__ float As[8][128];  // [k=e][m=t]
    __shared__ float Bs[8][128];  // [k=e][n=h]
    const int b  = blockIdx.z;
    const int tB = blockIdx.y * 128;
    const int hB = blockIdx.x * 128;
    const int tid = threadIdx.x;
    const int m0 = (tid >> 4) << 3;
    const int n0 = (tid & 15) << 3;
    const int lr = tid >> 1;
    const int lk = (tid & 1) << 2;
    const float* Ag = g_ctx + (size_t)b * TT * EE;
    float acc[8][8] = {};
    for (int k0 = 0; k0 < EE; k0 += 8) {
        float4 av = *(const float4*)(Ag + (size_t)(tB + lr) * EE + k0 + lk);
        As[lk + 0][lr] = av.x; As[lk + 1][lr] = av.y;
        As[lk + 2][lr] = av.z; As[lk + 3][lr] = av.w;
        float4 bv = *(const float4*)(W + (size_t)(hB + lr) * EE + k0 + lk);
        Bs[lk + 0][lr] = bv.x; Bs[lk + 1][lr] = bv.y;
        Bs[lk + 2][lr] = bv.z; Bs[lk + 3][lr] = bv.w;
        __syncthreads();
#pragma unroll
        for (int k = 0; k < 8; k++) {
            float a[8], bb[8];
            *(float4*)&a[0]  = *(const float4*)&As[k][m0];
            *(float4*)&a[4]  = *(const float4*)&As[k][m0 + 4];
            *(float4*)&bb[0] = *(const float4*)&Bs[k][n0];
            *(float4*)&bb[4] = *(const float4*)&Bs[k][n0 + 4];
#pragma unroll
            for (int i = 0; i < 8; i++)
#pragma unroll
                for (int j = 0; j < 8; j++) acc[i][j] = fmaf(a[i], bb[j], acc[i][j]);
        }
        __syncthreads();
    }
#pragma unroll
    for (int j = 0; j < 8; j++) {
        const int h = hB + n0 + j;
        const float bh = bias[h];
        const size_t base = ((size_t)b * HH + h) * TT + tB + m0;
#pragma unroll
        for (int i = 0; i < 8; i += 4) {
            float4 dv = *(const float4*)(dec + base + i);
            float4 o;
            o.x = SCALE * (acc[i + 0][j] + bh + dv.x);
            o.y = SCALE * (acc[i + 1][j] + bh + dv.y);
            o.z = SCALE * (acc[i + 2][j] + bh + dv.z);
            o.w = SCALE * (acc[i + 3][j] + bh + dv.w);
            *(float4*)(out + base + i) = o;
        }
    }
}

extern "C" void kernel_launch(void* const* d_in, const int* in_sizes, int n_in,
                              void* d_out, int out_size)
{
    const float* dec  = (const float*)d_in[0];
    const float* emb  = (const float*)d_in[1];
    const float* enc  = (const float*)d_in[2];
    const float* enb  = (const float*)d_in[3];
    const float* Wh2e = (const float*)d_in[4];
    const float* bh2e = (const float*)d_in[5];
    const float* We2h = (const float*)d_in[6];
    const float* be2h = (const float*)d_in[7];
    float* a_out    = (float*)d_out;                       // [B,T,S]
    float* conv_out = a_out + (size_t)BB * TT * SS;        // [B,H,T]

    k1_q      <<<dim3(EE / 128, TT / 128, BB), 256>>>(dec, emb, Wh2e, bh2e);
    k2_energy <<<dim3(SS / 128, TT / 128, BB), 256>>>(enc, a_out);
    k3_softmax<<<BB * TT, 256>>>(a_out);
    k4_context<<<dim3(EE / 128, TT / 128, BB), 256>>>(a_out, enb);
    k5_out    <<<dim3(HH / 128, TT / 128, BB), 256>>>(dec, We2h, be2h, conv_out);
}

// round 2
// speedup vs baseline: 1.0018x; 1.0018x over previous
#include <cuda_runtime.h>

// Problem constants
#define BB 8
#define HH 512
#define EE 256
#define TT 2048
#define SS 2048
#define SCALE 0.8366600265340756f  // sqrt(0.7)

// Scratch (device globals — no allocation allowed in kernel_launch)
__device__ float g_Q[BB * TT * EE];    // 16.8 MB
__device__ float g_ctx[BB * TT * EE];  // 16.8 MB

typedef unsigned long long ull;

__device__ __forceinline__ ull ffma2(ull a, ull b, ull c) {
    ull d;
    asm("fma.rn.f32x2 %0, %1, %2, %3;" : "=l"(d) : "l"(a), "l"(b), "l"(c));
    return d;
}
__device__ __forceinline__ ull pack2(float x, float y) {
    ull d;
    asm("mov.b64 %0, {%1, %2};" : "=l"(d) : "f"(x), "f"(y));
    return d;
}
__device__ __forceinline__ float2 unpack2(ull v) {
    float2 r;
    asm("mov.b64 {%0, %1}, %2;" : "=f"(r.x), "=f"(r.y) : "l"(v));
    return r;
}

// Shared FFMA2 micro-loop: 8 m-rows x 4 j-pairs, K-tile of 8.
// As/Bs: [8][128] k-major SMEM tiles; m0/n0: per-thread offsets.
// acc: ull[8][4] packed (j, j+1) accumulators.
#define MICRO_LOOP(As, Bs, m0, n0, acc)                                      \
    _Pragma("unroll")                                                        \
    for (int k = 0; k < 8; k++) {                                            \
        float a8[8];                                                         \
        *(float4*)&a8[0] = *(const float4*)&As[k][m0];                       \
        *(float4*)&a8[4] = *(const float4*)&As[k][m0 + 4];                   \
        ull b4[4];                                                           \
        {                                                                    \
            ulonglong2 q0 = *(const ulonglong2*)&Bs[k][n0];                  \
            ulonglong2 q1 = *(const ulonglong2*)&Bs[k][n0 + 4];              \
            b4[0] = q0.x; b4[1] = q0.y; b4[2] = q1.x; b4[3] = q1.y;          \
        }                                                                    \
        _Pragma("unroll")                                                    \
        for (int i = 0; i < 8; i++) {                                        \
            ull ad = pack2(a8[i], a8[i]);                                    \
            _Pragma("unroll")                                                \
            for (int jp = 0; jp < 4; jp++)                                   \
                acc[i][jp] = ffma2(ad, b4[jp], acc[i][jp]);                  \
        }                                                                    \
    }

#define UNPACK_ACC(acc, accf)                                                \
    _Pragma("unroll")                                                        \
    for (int i = 0; i < 8; i++) {                                            \
        _Pragma("unroll")                                                    \
        for (int jp = 0; jp < 4; jp++) {                                     \
            float2 t = unpack2(acc[i][jp]);                                  \
            accf[i][2 * jp] = t.x; accf[i][2 * jp + 1] = t.y;                \
        }                                                                    \
    }

// ---- K1: Q[b,t,e] = SCALE * (sum_h dec[b,h,t]*W_h2e[e,h] + b_h2e[e] + embedd[b,t,e])
__global__ void __launch_bounds__(256) k1_q(
    const float* __restrict__ dec,   // [B,H,T]
    const float* __restrict__ emb,   // [B,T,E]
    const float* __restrict__ W,     // [E,H]
    const float* __restrict__ bias)  // [E]
{
    __shared__ float As[8][128];  // [k=h][m=t]
    __shared__ float Bs[8][128];  // [k=h][n=e]
    const int b  = blockIdx.z;
    const int tB = blockIdx.y * 128;
    const int eB = blockIdx.x * 128;
    const int tid = threadIdx.x;
    const int m0 = (tid >> 4) << 3;
    const int n0 = (tid & 15) << 3;
    const int a_h = tid >> 5;            // 0..7
    const int a_t = (tid & 31) << 2;     // 0..124
    const int b_e = tid >> 1;            // 0..127
    const int b_h = (tid & 1) << 2;      // 0 or 4
    const float* Ag = dec + (size_t)b * HH * TT;
    ull acc[8][4] = {};
    for (int k0 = 0; k0 < HH; k0 += 8) {
        float4 av = *(const float4*)(Ag + (size_t)(k0 + a_h) * TT + tB + a_t);
        *(float4*)&As[a_h][a_t] = av;
        float4 bv = *(const float4*)(W + (size_t)(eB + b_e) * HH + k0 + b_h);
        Bs[b_h + 0][b_e] = bv.x; Bs[b_h + 1][b_e] = bv.y;
        Bs[b_h + 2][b_e] = bv.z; Bs[b_h + 3][b_e] = bv.w;
        __syncthreads();
        MICRO_LOOP(As, Bs, m0, n0, acc)
        __syncthreads();
    }
    float accf[8][8];
    UNPACK_ACC(acc, accf)
#pragma unroll
    for (int i = 0; i < 8; i++) {
        const int t = tB + m0 + i;
        const size_t rowo = ((size_t)b * TT + t) * EE;
#pragma unroll
        for (int j = 0; j < 8; j += 4) {
            const int e = eB + n0 + j;
            float4 ev = *(const float4*)(emb + rowo + e);
            float4 bi = *(const float4*)(bias + e);
            float4 o;
            o.x = SCALE * (accf[i][j + 0] + bi.x + ev.x);
            o.y = SCALE * (accf[i][j + 1] + bi.y + ev.y);
            o.z = SCALE * (accf[i][j + 2] + bi.z + ev.z);
            o.w = SCALE * (accf[i][j + 3] + bi.w + ev.w);
            *(float4*)(g_Q + rowo + e) = o;
        }
    }
}

// ---- K2: energy[b,t,s] = sum_e Q[b,t,e] * K[b,s,e]   (written raw into a_out)
__global__ void __launch_bounds__(256) k2_energy(
    const float* __restrict__ Kmat,  // en_conved [B,S,E]
    float* __restrict__ a_out)       // [B,T,S]
{
    __shared__ float As[8][128];  // [k=e][m=t]
    __shared__ float Bs[8][128];  // [k=e][n=s]
    const int b  = blockIdx.z;
    const int tB = blockIdx.y * 128;
    const int sB = blockIdx.x * 128;
    const int tid = threadIdx.x;
    const int m0 = (tid >> 4) << 3;
    const int n0 = (tid & 15) << 3;
    const int lr = tid >> 1;          // 0..127
    const int lk = (tid & 1) << 2;    // 0 or 4
    const float* Qg = g_Q + (size_t)b * TT * EE;
    const float* Kg = Kmat + (size_t)b * SS * EE;
    ull acc[8][4] = {};
    for (int k0 = 0; k0 < EE; k0 += 8) {
        float4 av = *(const float4*)(Qg + (size_t)(tB + lr) * EE + k0 + lk);
        As[lk + 0][lr] = av.x; As[lk + 1][lr] = av.y;
        As[lk + 2][lr] = av.z; As[lk + 3][lr] = av.w;
        float4 bv = *(const float4*)(Kg + (size_t)(sB + lr) * EE + k0 + lk);
        Bs[lk + 0][lr] = bv.x; Bs[lk + 1][lr] = bv.y;
        Bs[lk + 2][lr] = bv.z; Bs[lk + 3][lr] = bv.w;
        __syncthreads();
        MICRO_LOOP(As, Bs, m0, n0, acc)
        __syncthreads();
    }
    float accf[8][8];
    UNPACK_ACC(acc, accf)
#pragma unroll
    for (int i = 0; i < 8; i++) {
        float* row = a_out + ((size_t)b * TT + tB + m0 + i) * SS + sB + n0;
#pragma unroll
        for (int j = 0; j < 8; j += 4) {
            float4 o = {accf[i][j], accf[i][j + 1], accf[i][j + 2], accf[i][j + 3]};
            *(float4*)(row + j) = o;
        }
    }
}

// ---- K3: in-place row softmax over S
__global__ void __launch_bounds__(256) k3_softmax(float* __restrict__ a)
{
    const size_t row = blockIdx.x;
    float* p = a + row * SS;
    const int tid = threadIdx.x;
    float v[8];
#pragma unroll
    for (int i = 0; i < 8; i++) v[i] = p[tid + (i << 8)];
    float m = v[0];
#pragma unroll
    for (int i = 1; i < 8; i++) m = fmaxf(m, v[i]);
#pragma unroll
    for (int o = 16; o > 0; o >>= 1) m = fmaxf(m, __shfl_xor_sync(0xffffffffu, m, o));
    __shared__ float red[8];
    if ((tid & 31) == 0) red[tid >> 5] = m;
    __syncthreads();
    float M = red[0];
#pragma unroll
    for (int i = 1; i < 8; i++) M = fmaxf(M, red[i]);
    float s = 0.f;
#pragma unroll
    for (int i = 0; i < 8; i++) { v[i] = expf(v[i] - M); s += v[i]; }
#pragma unroll
    for (int o = 16; o > 0; o >>= 1) s += __shfl_xor_sync(0xffffffffu, s, o);
    __syncthreads();  // protect red[] reuse
    if ((tid & 31) == 0) red[tid >> 5] = s;
    __syncthreads();
    float Z = 0.f;
#pragma unroll
    for (int i = 0; i < 8; i++) Z += red[i];
    const float inv = 1.f / Z;
#pragma unroll
    for (int i = 0; i < 8; i++) p[tid + (i << 8)] = v[i] * inv;
}

// ---- K4: ctx[b,t,e] = sum_s a[b,t,s] * V[b,s,e]
__global__ void __launch_bounds__(256) k4_context(
    const float* __restrict__ a,  // [B,T,S] normalized
    const float* __restrict__ V)  // en_combined [B,S,E]
{
    __shared__ float As[8][128];  // [k=s][m=t]
    __shared__ float Bs[8][128];  // [k=s][n=e]
    const int b  = blockIdx.z;
    const int tB = blockIdx.y * 128;
    const int eB = blockIdx.x * 128;
    const int tid = threadIdx.x;
    const int m0 = (tid >> 4) << 3;
    const int n0 = (tid & 15) << 3;
    const int la_r = tid >> 1;          // 0..127
    const int la_k = (tid & 1) << 2;    // 0 or 4
    const int lb_s = tid >> 5;          // 0..7
    const int lb_e = (tid & 31) << 2;   // 0..124
    const float* Ag = a + (size_t)b * TT * SS;
    const float* Vg = V + (size_t)b * SS * EE;
    ull acc[8][4] = {};
    for (int k0 = 0; k0 < SS; k0 += 8) {
        float4 av = *(const float4*)(Ag + (size_t)(tB + la_r) * SS + k0 + la_k);
        As[la_k + 0][la_r] = av.x; As[la_k + 1][la_r] = av.y;
        As[la_k + 2][la_r] = av.z; As[la_k + 3][la_r] = av.w;
        float4 bv = *(const float4*)(Vg + (size_t)(k0 + lb_s) * EE + eB + lb_e);
        *(float4*)&Bs[lb_s][lb_e] = bv;
        __syncthreads();
        MICRO_LOOP(As, Bs, m0, n0, acc)
        __syncthreads();
    }
    float accf[8][8];
    UNPACK_ACC(acc, accf)
#pragma unroll
    for (int i = 0; i < 8; i++) {
        const size_t rowo = ((size_t)b * TT + tB + m0 + i) * EE;
#pragma unroll
        for (int j = 0; j < 8; j += 4) {
            float4 o = {accf[i][j], accf[i][j + 1], accf[i][j + 2], accf[i][j + 3]};
            *(float4*)(g_ctx + rowo + eB + n0 + j) = o;
        }
    }
}

// ---- K5: out[b,h,t] = SCALE*(sum_e ctx[b,t,e]*W_e2h[h,e] + b_e2h[h] + dec[b,h,t])
__global__ void __launch_bounds__(256) k5_out(
    const float* __restrict__ dec,   // [B,H,T]
    const float* __restrict__ W,     // [H,E]
    const float* __restrict__ bias,  // [H]
    float* __restrict__ out)         // [B,H,T]
{
    __shared__ float As[8][128];  // [k=e][m=t]
    __shared__ float Bs[8][128];  // [k=e][n=h]
    const int b  = blockIdx.z;
    const int tB = blockIdx.y * 128;
    const int hB = blockIdx.x * 128;
    const int tid = threadIdx.x;
    const int m0 = (tid >> 4) << 3;
    const int n0 = (tid & 15) << 3;
    const int lr = tid >> 1;
    const int lk = (tid & 1) << 2;
    const float* Ag = g_ctx + (size_t)b * TT * EE;
    ull acc[8][4] = {};
    for (int k0 = 0; k0 < EE; k0 += 8) {
        float4 av = *(const float4*)(Ag + (size_t)(tB + lr) * EE + k0 + lk);
        As[lk + 0][lr] = av.x; As[lk + 1][lr] = av.y;
        As[lk + 2][lr] = av.z; As[lk + 3][lr] = av.w;
        float4 bv = *(const float4*)(W + (size_t)(hB + lr) * EE + k0 + lk);
        Bs[lk + 0][lr] = bv.x; Bs[lk + 1][lr] = bv.y;
        Bs[lk + 2][lr] = bv.z; Bs[lk + 3][lr] = bv.w;
        __syncthreads();
        MICRO_LOOP(As, Bs, m0, n0, acc)
        __syncthreads();
    }
    float accf[8][8];
    UNPACK_ACC(acc, accf)
#pragma unroll
    for (int j = 0; j < 8; j++) {
        const int h = hB + n0 + j;
        const float bh = bias[h];
        const size_t base = ((size_t)b * HH + h) * TT + tB + m0;
#pragma unroll
        for (int i = 0; i < 8; i += 4) {
            float4 dv = *(const float4*)(dec + base + i);
            float4 o;
            o.x = SCALE * (accf[i + 0][j] + bh + dv.x);
            o.y = SCALE * (accf[i + 1][j] + bh + dv.y);
            o.z = SCALE * (accf[i + 2][j] + bh + dv.z);
            o.w = SCALE * (accf[i + 3][j] + bh + dv.w);
            *(float4*)(out + base + i) = o;
        }
    }
}

extern "C" void kernel_launch(void* const* d_in, const int* in_sizes, int n_in,
                              void* d_out, int out_size)
{
    const float* dec  = (const float*)d_in[0];
    const float* emb  = (const float*)d_in[1];
    const float* enc  = (const float*)d_in[2];
    const float* enb  = (const float*)d_in[3];
    const float* Wh2e = (const float*)d_in[4];
    const float* bh2e = (const float*)d_in[5];
    const float* We2h = (const float*)d_in[6];
    const float* be2h = (const float*)d_in[7];
    float* a_out    = (float*)d_out;                       // [B,T,S]
    float* conv_out = a_out + (size_t)BB * TT * SS;        // [B,H,T]

    k1_q      <<<dim3(EE / 128, TT / 128, BB), 256>>>(dec, emb, Wh2e, bh2e);
    k2_energy <<<dim3(SS / 128, TT / 128, BB), 256>>>(enc, a_out);
    k3_softmax<<<BB * TT, 256>>>(a_out);
    k4_context<<<dim3(EE / 128, TT / 128, BB), 256>>>(a_out, enb);
    k5_out    <<<dim3(HH / 128, TT / 128, BB), 256>>>(dec, We2h, be2h, conv_out);
}

// round 4
// speedup vs baseline: 1.3219x; 1.3196x over previous
#include <cuda_runtime.h>
#include <cstdint>

// Problem constants
#define BB 8
#define HH 512
#define EE 256
#define TT 2048
#define SS 2048
#define SCALE 0.8366600265340756f  // sqrt(0.7)

// Scratch (device globals — no allocation allowed in kernel_launch)
__device__ float g_Q[BB * TT * EE];    // 16.8 MB
__device__ float g_ctx[BB * TT * EE];  // 16.8 MB
__device__ float g_Vt[BB * EE * SS];   // 16.8 MB (en_combined transposed)

__device__ __forceinline__ float tf32r(float x) {
    uint32_t u;
    asm("cvt.rna.tf32.f32 %0, %1;" : "=r"(u) : "f"(x));
    return __uint_as_float(u);
}
__device__ __forceinline__ void mma8(float* c, const uint32_t* a, const uint32_t* b) {
    asm volatile("mma.sync.aligned.m16n8k8.row.col.f32.tf32.tf32.f32 "
        "{%0,%1,%2,%3}, {%4,%5,%6,%7}, {%8,%9}, {%0,%1,%2,%3};"
        : "+f"(c[0]), "+f"(c[1]), "+f"(c[2]), "+f"(c[3])
        : "r"(a[0]), "r"(a[1]), "r"(a[2]), "r"(a[3]), "r"(b[0]), "r"(b[1]));
}
#define FU(x) __float_as_uint(x)

// ==================== 3xTF32 GEMM: C[128,128] tile, mma.sync ====================
// C[m,n] = sum_k A[m,k] * B[n,k]  (both K-major).
// Block 128 threads = 4 warps (2x2), warp tile 64x64, BK=32.
#define QP 36  // SMEM row pitch in floats (32 + 4): conflict-free frag loads
#define GEMM_SMEM (4 * 128 * QP * 4)  // 73728 B

__global__ void __launch_bounds__(128, 2) gemm3x(
    const float* __restrict__ A, int lda, size_t sA,
    const float* __restrict__ B, int ldb, size_t sB,
    float* __restrict__ C, int ldc, size_t sC, int K)
{
    extern __shared__ float sm[];
    float* AH = sm;
    float* AL = sm + 128 * QP;
    float* BH = sm + 2 * 128 * QP;
    float* BL = sm + 3 * 128 * QP;

    const int tid  = threadIdx.x;
    const int lane = tid & 31;
    const int wid  = tid >> 5;
    const int wm   = wid >> 1;       // 0..1
    const int wn   = wid & 1;        // 0..1
    const int mB   = wm * 64;
    const int nB   = wn * 64;
    const int g    = lane >> 2;      // groupID 0..7
    const int tg   = lane & 3;       // thread in group 0..3

    const int ldr = tid >> 3;        // 0..15 (row sub-index for tile loads)
    const int ldk = (tid & 7) << 2;  // 0,4,...,28

    const float* Ab = A + blockIdx.z * sA + (size_t)(blockIdx.y * 128) * lda;
    const float* Bb = B + blockIdx.z * sB + (size_t)(blockIdx.x * 128) * ldb;

    float acc[4][8][4] = {};  // [mi][ni][reg]

    for (int k0 = 0; k0 < K; k0 += 32) {
        __syncthreads();
        // ---- load 128x32 A and B tiles, split hi/lo, store to SMEM ----
#pragma unroll
        for (int it = 0; it < 8; it++) {
            const int row = it * 16 + ldr;
            float4 v = *(const float4*)(Ab + (size_t)row * lda + k0 + ldk);
            float4 h, l;
            h.x = tf32r(v.x); l.x = tf32r(v.x - h.x);
            h.y = tf32r(v.y); l.y = tf32r(v.y - h.y);
            h.z = tf32r(v.z); l.z = tf32r(v.z - h.z);
            h.w = tf32r(v.w); l.w = tf32r(v.w - h.w);
            *(float4*)&AH[row * QP + ldk] = h;
            *(float4*)&AL[row * QP + ldk] = l;
            v = *(const float4*)(Bb + (size_t)row * ldb + k0 + ldk);
            h.x = tf32r(v.x); l.x = tf32r(v.x - h.x);
            h.y = tf32r(v.y); l.y = tf32r(v.y - h.y);
            h.z = tf32r(v.z); l.z = tf32r(v.z - h.z);
            h.w = tf32r(v.w); l.w = tf32r(v.w - h.w);
            *(float4*)&BH[row * QP + ldk] = h;
            *(float4*)&BL[row * QP + ldk] = l;
        }
        __syncthreads();

        // ---- 4 k8 sub-steps ----
#pragma unroll
        for (int ks = 0; ks < 4; ks++) {
            const int kc = ks * 8 + tg;
            uint32_t ah[4][4], al[4][4];
#pragma unroll
            for (int mi = 0; mi < 4; mi++) {
                const int r0 = (mB + mi * 16 + g) * QP;
                const int r1 = r0 + 8 * QP;
                ah[mi][0] = FU(AH[r0 + kc]);
                ah[mi][1] = FU(AH[r1 + kc]);
                ah[mi][2] = FU(AH[r0 + kc + 4]);
                ah[mi][3] = FU(AH[r1 + kc + 4]);
                al[mi][0] = FU(AL[r0 + kc]);
                al[mi][1] = FU(AL[r1 + kc]);
                al[mi][2] = FU(AL[r0 + kc + 4]);
                al[mi][3] = FU(AL[r1 + kc + 4]);
            }
            uint32_t bh[8][2], bl[8][2];
#pragma unroll
            for (int ni = 0; ni < 8; ni++) {
                const int n0 = (nB + ni * 8 + g) * QP;
                bh[ni][0] = FU(BH[n0 + kc]);
                bh[ni][1] = FU(BH[n0 + kc + 4]);
                bl[ni][0] = FU(BL[n0 + kc]);
                bl[ni][1] = FU(BL[n0 + kc + 4]);
            }
#pragma unroll
            for (int mi = 0; mi < 4; mi++)
#pragma unroll
                for (int ni = 0; ni < 8; ni++) {
                    mma8(acc[mi][ni], ah[mi], bh[ni]);
                    mma8(acc[mi][ni], ah[mi], bl[ni]);
                    mma8(acc[mi][ni], al[mi], bh[ni]);
                }
        }
    }

    // ---- epilogue ----
    float* Cb = C + blockIdx.z * sC;
#pragma unroll
    for (int mi = 0; mi < 4; mi++) {
        const int r0 = blockIdx.y * 128 + mB + mi * 16 + g;
#pragma unroll
        for (int ni = 0; ni < 8; ni++) {
            const int cc = blockIdx.x * 128 + nB + ni * 8 + 2 * tg;
            float2 v0 = {acc[mi][ni][0], acc[mi][ni][1]};
            float2 v1 = {acc[mi][ni][2], acc[mi][ni][3]};
            *(float2*)(Cb + (size_t)r0 * ldc + cc) = v0;
            *(float2*)(Cb + (size_t)(r0 + 8) * ldc + cc) = v1;
        }
    }
}

// ==================== K0: transpose V[b,s,e] -> Vt[b,e,s] ====================
__global__ void __launch_bounds__(256) k0_transpose(
    const float* __restrict__ V, float* __restrict__ Vt)
{
    __shared__ float t[32][33];
    const int b = blockIdx.z;
    const int s0 = blockIdx.x * 32, e0 = blockIdx.y * 32;
    const float* Vb = V + (size_t)b * SS * EE;
    float* Vtb = Vt + (size_t)b * EE * SS;
    const int x = threadIdx.x, y = threadIdx.y;
#pragma unroll
    for (int i = 0; i < 32; i += 8)
        t[y + i][x] = Vb[(size_t)(s0 + y + i) * EE + e0 + x];
    __syncthreads();
#pragma unroll
    for (int i = 0; i < 32; i += 8)
        Vtb[(size_t)(e0 + y + i) * SS + s0 + x] = t[x][y + i];
}

// ==================== K1: Q projection (SIMT fp32) ====================
__global__ void __launch_bounds__(256) k1_q(
    const float* __restrict__ dec,   // [B,H,T]
    const float* __restrict__ emb,   // [B,T,E]
    const float* __restrict__ W,     // [E,H]
    const float* __restrict__ bias)  // [E]
{
    __shared__ float As[8][128];
    __shared__ float Bs[8][128];
    const int b  = blockIdx.z;
    const int tB = blockIdx.y * 128;
    const int eB = blockIdx.x * 128;
    const int tid = threadIdx.x;
    const int m0 = (tid >> 4) << 3;
    const int n0 = (tid & 15) << 3;
    const int a_h = tid >> 5;
    const int a_t = (tid & 31) << 2;
    const int b_e = tid >> 1;
    const int b_h = (tid & 1) << 2;
    const float* Ag = dec + (size_t)b * HH * TT;
    float acc[8][8] = {};
    for (int k0 = 0; k0 < HH; k0 += 8) {
        float4 av = *(const float4*)(Ag + (size_t)(k0 + a_h) * TT + tB + a_t);
        *(float4*)&As[a_h][a_t] = av;
        float4 bv = *(const float4*)(W + (size_t)(eB + b_e) * HH + k0 + b_h);
        Bs[b_h + 0][b_e] = bv.x; Bs[b_h + 1][b_e] = bv.y;
        Bs[b_h + 2][b_e] = bv.z; Bs[b_h + 3][b_e] = bv.w;
        __syncthreads();
#pragma unroll
        for (int k = 0; k < 8; k++) {
            float a[8], bb[8];
            *(float4*)&a[0]  = *(const float4*)&As[k][m0];
            *(float4*)&a[4]  = *(const float4*)&As[k][m0 + 4];
            *(float4*)&bb[0] = *(const float4*)&Bs[k][n0];
            *(float4*)&bb[4] = *(const float4*)&Bs[k][n0 + 4];
#pragma unroll
            for (int i = 0; i < 8; i++)
#pragma unroll
                for (int j = 0; j < 8; j++) acc[i][j] = fmaf(a[i], bb[j], acc[i][j]);
        }
        __syncthreads();
    }
#pragma unroll
    for (int i = 0; i < 8; i++) {
        const size_t rowo = ((size_t)b * TT + tB + m0 + i) * EE;
#pragma unroll
        for (int j = 0; j < 8; j += 4) {
            const int e = eB + n0 + j;
            float4 ev = *(const float4*)(emb + rowo + e);
            float4 bi = *(const float4*)(bias + e);
            float4 o;
            o.x = SCALE * (acc[i][j + 0] + bi.x + ev.x);
            o.y = SCALE * (acc[i][j + 1] + bi.y + ev.y);
            o.z = SCALE * (acc[i][j + 2] + bi.z + ev.z);
            o.w = SCALE * (acc[i][j + 3] + bi.w + ev.w);
            *(float4*)(g_Q + rowo + e) = o;
        }
    }
}

// ==================== K3: softmax ====================
__global__ void __launch_bounds__(256) k3_softmax(float* __restrict__ a)
{
    const size_t row = blockIdx.x;
    float* p = a + row * SS;
    const int tid = threadIdx.x;
    float v[8];
#pragma unroll
    for (int i = 0; i < 8; i++) v[i] = p[tid + (i << 8)];
    float m = v[0];
#pragma unroll
    for (int i = 1; i < 8; i++) m = fmaxf(m, v[i]);
#pragma unroll
    for (int o = 16; o > 0; o >>= 1) m = fmaxf(m, __shfl_xor_sync(0xffffffffu, m, o));
    __shared__ float red[8];
    if ((tid & 31) == 0) red[tid >> 5] = m;
    __syncthreads();
    float M = red[0];
#pragma unroll
    for (int i = 1; i < 8; i++) M = fmaxf(M, red[i]);
    float s = 0.f;
#pragma unroll
    for (int i = 0; i < 8; i++) { v[i] = __expf(v[i] - M); s += v[i]; }
#pragma unroll
    for (int o = 16; o > 0; o >>= 1) s += __shfl_xor_sync(0xffffffffu, s, o);
    __syncthreads();
    if ((tid & 31) == 0) red[tid >> 5] = s;
    __syncthreads();
    float Z = 0.f;
#pragma unroll
    for (int i = 0; i < 8; i++) Z += red[i];
    const float inv = 1.f / Z;
#pragma unroll
    for (int i = 0; i < 8; i++) p[tid + (i << 8)] = v[i] * inv;
}

// ==================== K5: output projection (SIMT fp32) ====================
__global__ void __launch_bounds__(256) k5_out(
    const float* __restrict__ dec,   // [B,H,T]
    const float* __restrict__ W,     // [H,E]
    const float* __restrict__ bias,  // [H]
    float* __restrict__ out)         // [B,H,T]
{
    __shared__ float As[8][128];
    __shared__ float Bs[8][128];
    const int b  = blockIdx.z;
    const int tB = blockIdx.y * 128;
    const int hB = blockIdx.x * 128;
    const int tid = threadIdx.x;
    const int m0 = (tid >> 4) << 3;
    const int n0 = (tid & 15) << 3;
    const int lr = tid >> 1;
    const int lk = (tid & 1) << 2;
    const float* Ag = g_ctx + (size_t)b * TT * EE;
    float acc[8][8] = {};
    for (int k0 = 0; k0 < EE; k0 += 8) {
        float4 av = *(const float4*)(Ag + (size_t)(tB + lr) * EE + k0 + lk);
        As[lk + 0][lr] = av.x; As[lk + 1][lr] = av.y;
        As[lk + 2][lr] = av.z; As[lk + 3][lr] = av.w;
        float4 bv = *(const float4*)(W + (size_t)(hB + lr) * EE + k0 + lk);
        Bs[lk + 0][lr] = bv.x; Bs[lk + 1][lr] = bv.y;
        Bs[lk + 2][lr] = bv.z; Bs[lk + 3][lr] = bv.w;
        __syncthreads();
#pragma unroll
        for (int k = 0; k < 8; k++) {
            float a[8], bb[8];
            *(float4*)&a[0]  = *(const float4*)&As[k][m0];
            *(float4*)&a[4]  = *(const float4*)&As[k][m0 + 4];
            *(float4*)&bb[0] = *(const float4*)&Bs[k][n0];
            *(float4*)&bb[4] = *(const float4*)&Bs[k][n0 + 4];
#pragma unroll
            for (int i = 0; i < 8; i++)
#pragma unroll
                for (int j = 0; j < 8; j++) acc[i][j] = fmaf(a[i], bb[j], acc[i][j]);
        }
        __syncthreads();
    }
#pragma unroll
    for (int j = 0; j < 8; j++) {
        const int h = hB + n0 + j;
        const float bh = bias[h];
        const size_t base = ((size_t)b * HH + h) * TT + tB + m0;
#pragma unroll
        for (int i = 0; i < 8; i += 4) {
            float4 dv = *(const float4*)(dec + base + i);
            float4 o;
            o.x = SCALE * (acc[i + 0][j] + bh + dv.x);
            o.y = SCALE * (acc[i + 1][j] + bh + dv.y);
            o.z = SCALE * (acc[i + 2][j] + bh + dv.z);
            o.w = SCALE * (acc[i + 3][j] + bh + dv.w);
            *(float4*)(out + base + i) = o;
        }
    }
}

extern "C" void kernel_launch(void* const* d_in, const int* in_sizes, int n_in,
                              void* d_out, int out_size)
{
    const float* dec  = (const float*)d_in[0];
    const float* emb  = (const float*)d_in[1];
    const float* enc  = (const float*)d_in[2];
    const float* enb  = (const float*)d_in[3];
    const float* Wh2e = (const float*)d_in[4];
    const float* bh2e = (const float*)d_in[5];
    const float* We2h = (const float*)d_in[6];
    const float* be2h = (const float*)d_in[7];
    float* a_out    = (float*)d_out;                 // [B,T,S]
    float* conv_out = a_out + (size_t)BB * TT * SS;  // [B,H,T]

    cudaFuncSetAttribute(gemm3x, cudaFuncAttributeMaxDynamicSharedMemorySize, GEMM_SMEM);

    float* Qp   = nullptr; cudaGetSymbolAddress((void**)&Qp,   g_Q);
    float* Ctxp = nullptr; cudaGetSymbolAddress((void**)&Ctxp, g_ctx);
    float* Vtp  = nullptr; cudaGetSymbolAddress((void**)&Vtp,  g_Vt);

    k0_transpose<<<dim3(SS / 32, EE / 32, BB), dim3(32, 8)>>>(enb, Vtp);
    k1_q<<<dim3(EE / 128, TT / 128, BB), 256>>>(dec, emb, Wh2e, bh2e);

    // K2: energy = Q @ K^T -> a_out (raw)
    gemm3x<<<dim3(SS / 128, TT / 128, BB), 128, GEMM_SMEM>>>(
        Qp, EE, (size_t)TT * EE,
        enc, EE, (size_t)SS * EE,
        a_out, SS, (size_t)TT * SS,
        EE);

    k3_softmax<<<BB * TT, 256>>>(a_out);

    // K4: ctx = a @ V (V transposed to K-major)
    gemm3x<<<dim3(EE / 128, TT / 128, BB), 128, GEMM_SMEM>>>(
        a_out, SS, (size_t)TT * SS,
        Vtp, SS, (size_t)EE * SS,
        Ctxp, EE, (size_t)TT * EE,
        SS);

    k5_out<<<dim3(HH / 128, TT / 128, BB), 256>>>(dec, We2h, be2h, conv_out);
}